// round 15
// baseline (speedup 1.0000x reference)
#include <cuda_runtime.h>
#include <math.h>

#define LL     1632
#define NUP    8
#define NB     32
#define NA     64
#define RED    408
#define RWS    4

typedef unsigned long long ull;

// ---------------- scratch (device globals) -----------------------------------
__device__ float2 g_phtab[LL];          // e^{2*pi*i*q/L}
__device__ float2 g_b12[12];            // e^{2*pi*i*r/12}
__device__ ull    g_wtc[5*416];         // odd bins o=1,3,5,7,9: packed {cos(2p),cos(2p+1)}
__device__ ull    g_wts[5*416];         // packed {sin(2p),sin(2p+1)}
__device__ int    g_m[NUP*NB];
__device__ ull    g_Weff2[NUP*NB*180];  // per (u,b): 3 classes x 12 x 5, packed {w,w}
__device__ float  g_win[2048*21];
__device__ float  g_noise[2048];

// ---------------- f32x2 helpers ----------------------------------------------
__device__ __forceinline__ ull pk2(float a, float b) {
    ull r; asm("mov.b64 %0, {%1, %2};" : "=l"(r) : "f"(a), "f"(b)); return r;
}
__device__ __forceinline__ float2 up2(ull v) {
    float2 r; asm("mov.b64 {%0, %1}, %2;" : "=f"(r.x), "=f"(r.y) : "l"(v)); return r;
}
__device__ __forceinline__ ull fma2_(ull a, ull b, ull c) {
    ull d; asm("fma.rn.f32x2 %0, %1, %2, %3;" : "=l"(d) : "l"(a), "l"(b), "l"(c)); return d;
}
__device__ __forceinline__ ull mul2_(ull a, ull b) {
    ull d; asm("mul.rn.f32x2 %0, %1, %2;" : "=l"(d) : "l"(a), "l"(b)); return d;
}
__device__ __forceinline__ ull add2_(ull a, ull b) {
    ull d; asm("add.rn.f32x2 %0, %1, %2;" : "=l"(d) : "l"(a), "l"(b)); return d;
}
__device__ __forceinline__ ull sub2_(ull a, ull b) {
    ull d; asm("sub.rn.f32x2 %0, %1, %2;" : "=l"(d) : "l"(a), "l"(b)); return d;
}

// ---------------- kernel P: tables -------------------------------------------
__global__ void kP() {
    int i = blockIdx.x * blockDim.x + threadIdx.x;
    const double TP = 6.283185307179586476925286766559;
    if (i < LL) {
        double ang = TP * (double)i / (double)LL;
        g_phtab[i] = make_float2((float)cos(ang), (float)sin(ang));
    }
    if (i < 12) {
        double ang = TP * (double)i / 12.0;
        g_b12[i] = make_float2((float)cos(ang), (float)sin(ang));
    }
    if (i < 5 * 416) {
        int o5 = i / 416, p = i % 416;
        int o = 2 * o5 + 1;
        long n1 = 2 * p, n2 = 2 * p + 1;
        double a1 = TP * (double)(n1 * o) / (double)LL;
        double a2 = TP * (double)(n2 * o) / (double)LL;
        g_wtc[i] = pk2((float)cos(a1), (float)cos(a2));
        g_wts[i] = pk2((float)sin(a1), (float)sin(a2));
    }
}

// ---------------- kernel A ----------------------------------------------------
__device__ __forceinline__ float wred(float v) {
    #pragma unroll
    for (int off = 16; off; off >>= 1) v += __shfl_xor_sync(0xffffffffu, v, off);
    return v;
}

// core packed accumulate given x-pair, mirror-pair, base twiddle index r0, table index p
#define PAIR_BODY(p_, r_, Xr_, Xi_, MR_, MI_) do {                              \
    ull bx = bpx[r_], by = bpy[r_], byn = bpyn[r_];                             \
    ull xr_ = pk2((Xr_).x, (Xr_).y), xi_ = pk2((Xi_).x, (Xi_).y);               \
    ull gr = fma2_(xi_, byn, mul2_(xr_, bx));                                   \
    ull gi = fma2_(xi_, bx,  mul2_(xr_, by));                                   \
    ull hr = fma2_((MI_), by,  mul2_((MR_), bx));                               \
    ull hi = fma2_((MI_), bx,  mul2_((MR_), byn));                              \
    ull sr = add2_(gr, hr), dr = sub2_(gr, hr);                                 \
    ull si = add2_(gi, hi), di = sub2_(gi, hi);                                 \
    strp = add2_(strp, sr); stip = add2_(stip, si);                             \
    ull w1c = wtc[p_],        w1s = wts[p_];                                    \
    ull w3c = wtc[416 + p_],  w3s = wts[416 + p_];                              \
    ull w5c = wtc[832 + p_],  w5s = wts[832 + p_];                              \
    ull w7c = wtc[1248 + p_], w7s = wts[1248 + p_];                             \
    ull w9c = wtc[1664 + p_], w9s = wts[1664 + p_];                             \
    PACC(0, w1c, w1s); PACC(2, w3c, w3s); PACC(4, w5c, w5s);                    \
    PACC(6, w7c, w7s); PACC(8, w9c, w9s);                                       \
    ull t, c2v, s2v, c4v, s4v;                                                  \
    t = add2_(w1c, w1c); c2v = fma2_(t, w1c, NEG1); s2v = mul2_(t, w1s); PACC(1, c2v, s2v); \
    t = add2_(c2v, c2v); c4v = fma2_(t, c2v, NEG1); s4v = mul2_(t, s2v); PACC(3, c4v, s4v); \
    t = add2_(w3c, w3c); ull c6v = fma2_(t, w3c, NEG1), s6v = mul2_(t, w3s); PACC(5, c6v, s6v); \
    t = add2_(c4v, c4v); ull c8v = fma2_(t, c4v, NEG1), s8v = mul2_(t, s4v); PACC(7, c8v, s8v); \
    t = add2_(w5c, w5c); ull cav = fma2_(t, w5c, NEG1), sav = mul2_(t, w5s); PACC(9, cav, sav); \
} while (0)

#define PACC(o, c, s) do { \
    A[o] = fma2_(sr, (c), A[o]); B[o] = fma2_(dr, (s), B[o]); \
    C[o] = fma2_(si, (c), C[o]); D[o] = fma2_(di, (s), D[o]); } while (0)

__global__ __launch_bounds__(256, 2) void kA(const float* __restrict__ lsr,
                                             const float* __restrict__ lsi,
                                             const int*   __restrict__ cs) {
    __shared__ ull   wtc[5*416], wts[5*416];   // 33280 B, loaded once per block
    __shared__ ull   bpx[12], bpy[12], bpyn[12];
    __shared__ float wpart[8][22];             // per-warp partials (no atomics)

    const int tid  = threadIdx.x;
    const int bid  = blockIdx.x;        // bid = ub*8 + part
    const int part = bid & 7;
    const int ub   = bid >> 3;
    const int u    = ub >> 5;

    int k12 = (12 - (cs[u] % 12)) % 12; if (k12 < 0) k12 += 12;
    const int st = (4 * k12) % 12;      // 64*k12 mod 12

    for (int i = tid; i < 5*416; i += 256) { wtc[i] = g_wtc[i]; wts[i] = g_wts[i]; }
    if (tid < 12) {
        float2 b0 = g_b12[tid];
        float2 b1 = g_b12[(tid + k12) % 12];   // odd sample of pair
        bpx[tid]  = pk2(b0.x, b1.x);
        bpy[tid]  = pk2(b0.y, b1.y);
        bpyn[tid] = pk2(-b0.y, -b1.y);
    }
    __syncthreads();

    const int lane = tid & 31;
    const int warp = tid >> 5;
    const int a     = part * 8 + warp;
    const int base2 = (ub * 64 + a) * 816;     // float2 index base
    const float2* xr2p = (const float2*)lsr + base2;
    const float2* xi2p = (const float2*)lsi + base2;
    const float*  lrp  = lsr + 2 * base2;
    const float*  lip  = lsi + 2 * base2;

    ull A[10], B[10], C[10], D[10];
    #pragma unroll
    for (int o = 0; o < 10; ++o) { A[o]=0ull; B[o]=0ull; C[o]=0ull; D[o]=0ull; }
    ull strp = 0ull, stip = 0ull;
    float nacc = 0.f;
    const ull NEG1 = pk2(-1.f, -1.f);

    // ---- peel j=0 (p = 0..31; p=0 has no Mb partner) ----
    {
        const int p = lane;
        float2 Xr = xr2p[p],        Xi = xi2p[p];
        float2 Mar = xr2p[815 - p], Mai = xi2p[815 - p];
        float2 Mbr = make_float2(0.f, 0.f), Mbi = make_float2(0.f, 0.f);
        if (p >= 1) { Mbr = xr2p[816 - p]; Mbi = xi2p[816 - p]; }
        float er = lrp[2*p + 2], ei = lip[2*p + 2];
        float d;
        d = Xr.y - Xr.x;   nacc = fmaf(d, d, nacc);
        d = Xi.y - Xi.x;   nacc = fmaf(d, d, nacc);
        d = er - Xr.y;     nacc = fmaf(d, d, nacc);
        d = ei - Xi.y;     nacc = fmaf(d, d, nacc);
        d = Mar.y - Mar.x; nacc = fmaf(d, d, nacc);
        d = Mai.y - Mai.x; nacc = fmaf(d, d, nacc);
        if (p >= 1) {
            d = Mbr.x - Mar.y; nacc = fmaf(d, d, nacc);
            d = Mbi.x - Mai.y; nacc = fmaf(d, d, nacc);
        }
        ull MR = pk2(Mbr.x, Mar.y), MI = pk2(Mbi.x, Mai.y);
        const int r0 = (2 * p * k12) % 12;
        PAIR_BODY(p, r0, Xr, Xi, MR, MI);
    }

    // ---- branch-free main loop: j=1..11 (p = 32..383) ----
    int r = ((2 * (lane + 32)) * k12) % 12;
    for (int j = 1; j <= 11; ++j) {
        const int p = lane + (j << 5);
        float2 Xr = xr2p[p],        Xi = xi2p[p];
        float2 Mar = xr2p[815 - p], Mai = xi2p[815 - p];
        float2 Mbr = xr2p[816 - p], Mbi = xi2p[816 - p];
        float er = lrp[2*p + 2], ei = lip[2*p + 2];
        float d;
        d = Xr.y - Xr.x;   nacc = fmaf(d, d, nacc);
        d = Xi.y - Xi.x;   nacc = fmaf(d, d, nacc);
        d = er - Xr.y;     nacc = fmaf(d, d, nacc);
        d = ei - Xi.y;     nacc = fmaf(d, d, nacc);
        d = Mar.y - Mar.x; nacc = fmaf(d, d, nacc);
        d = Mai.y - Mai.x; nacc = fmaf(d, d, nacc);
        d = Mbr.x - Mar.y; nacc = fmaf(d, d, nacc);
        d = Mbi.x - Mai.y; nacc = fmaf(d, d, nacc);
        ull MR = pk2(Mbr.x, Mar.y), MI = pk2(Mbi.x, Mai.y);
        PAIR_BODY(p, r, Xr, Xi, MR, MI);
        r += st; if (r >= 12) r -= 12;
    }

    // ---- peel j=12 (p = 384..415; valid up to 408) ----
    {
        const int p = lane + 384;
        if (p <= 408) {
            const bool full = (p <= 407);
            float2 Xr = xr2p[p], Xi = xi2p[p];
            float2 Mar = make_float2(0.f,0.f), Mai = make_float2(0.f,0.f);
            float2 Mbr = make_float2(0.f,0.f), Mbi = make_float2(0.f,0.f);
            if (full) {
                Mar = xr2p[815 - p]; Mai = xi2p[815 - p];
                Mbr = xr2p[816 - p]; Mbi = xi2p[816 - p];
                float er = lrp[2*p + 2], ei = lip[2*p + 2];
                float d;
                d = Xr.y - Xr.x;   nacc = fmaf(d, d, nacc);
                d = Xi.y - Xi.x;   nacc = fmaf(d, d, nacc);
                d = er - Xr.y;     nacc = fmaf(d, d, nacc);
                d = ei - Xi.y;     nacc = fmaf(d, d, nacc);
                d = Mar.y - Mar.x; nacc = fmaf(d, d, nacc);
                d = Mai.y - Mai.x; nacc = fmaf(d, d, nacc);
                d = Mbr.x - Mar.y; nacc = fmaf(d, d, nacc);
                d = Mbi.x - Mai.y; nacc = fmaf(d, d, nacc);
            } else {
                // p == 408: only n=816 (self); n=817 is p=407's mirror
                Xr.y = 0.f; Xi.y = 0.f;
            }
            ull MR = pk2(Mbr.x, Mar.y), MI = pk2(Mbi.x, Mai.y);
            const int r0 = (2 * p * k12) % 12;
            PAIR_BODY(p, r0, Xr, Xi, MR, MI);
        }
    }

    // unpack packed accumulators and reduce
    float Af[10], Bf[10], Cf[10], Df[10];
    #pragma unroll
    for (int o = 0; o < 10; ++o) {
        float2 v;
        v = up2(A[o]); Af[o] = v.x + v.y;
        v = up2(B[o]); Bf[o] = v.x + v.y;
        v = up2(C[o]); Cf[o] = v.x + v.y;
        v = up2(D[o]); Df[o] = v.x + v.y;
    }
    float2 vv;
    vv = up2(strp);  float str = vv.x + vv.y;
    vv = up2(stip);  float sti = vv.x + vv.y;

    #pragma unroll
    for (int o = 0; o < 10; ++o) {
        Af[o]=wred(Af[o]); Bf[o]=wred(Bf[o]); Cf[o]=wred(Cf[o]); Df[o]=wred(Df[o]);
    }
    str=wred(str); sti=wred(sti); nacc=wred(nacc);

    if (lane == 0) {
        wpart[warp][10] = str*str + sti*sti;
        #pragma unroll
        for (int o = 0; o < 10; ++o) {
            float rp = Af[o]-Df[o], ip = Bf[o]+Cf[o];
            wpart[warp][11+o] = rp*rp + ip*ip;
            float rm = Af[o]+Df[o], im = Cf[o]-Bf[o];
            wpart[warp][9-o]  = rm*rm + im*im;
        }
        wpart[warp][21] = nacc;
    }
    __syncthreads();
    if (tid < 22) {
        float s = 0.f;
        #pragma unroll
        for (int w = 0; w < 8; ++w) s += wpart[w][tid];
        if (tid < 21) g_win[bid * 21 + tid] = s;
        else          g_noise[bid] = s;
    }
}

#undef PAIR_BODY
#undef PACC

// ---------------- kernel S: argmax + Wiener solve + packed Weff --------------
__global__ void kS(const int* __restrict__ cs) {
    __shared__ float win[21];
    __shared__ float Cm[144], Am[144], Iv[144], Wsh[144];
    __shared__ float s_sh;

    const int ub = blockIdx.x;
    const int tid = threadIdx.x;           // 144 threads
    const int u = ub >> 5;
    const int i = tid / 12, j = tid % 12;

    if (tid < 21) {
        float s = 0.f;
        #pragma unroll
        for (int p = 0; p < 8; ++p) s += g_win[(ub * 8 + p) * 21 + tid];
        win[tid] = s;
    }
    if (tid == 21) {
        float s = 0.f;
        #pragma unroll
        for (int p = 0; p < 8; ++p) s += g_noise[ub * 8 + p];
        s_sh = s / (64.0f * 1631.0f * 2.0f);
    }
    __syncthreads();

    if (tid == 0) {
        int bi = 0; float bv = win[0];
        for (int q = 1; q < 21; ++q) if (win[q] > bv) { bv = win[q]; bi = q; }
        int k12 = (12 - (cs[u] % 12)) % 12; if (k12 < 0) k12 += 12;
        g_m[ub] = k12 * 136 + (bi - 10);
    }

    int d = i - j; if (d < 0) d = -d;
    float c = (float)pow(0.9, (double)d);
    Cm[tid] = c;
    Am[tid] = c + ((i == j) ? s_sh : 0.f);
    Iv[tid] = (i == j) ? 1.f : 0.f;
    __syncthreads();

    for (int k = 0; k < 12; ++k) {
        float piv = Am[k * 12 + k];
        __syncthreads();
        if (i == k) {
            float ip = 1.0f / piv;
            Am[tid] *= ip; Iv[tid] *= ip;
        }
        __syncthreads();
        float f   = Am[i * 12 + k];
        float akj = Am[k * 12 + j];
        float ikj = Iv[k * 12 + j];
        __syncthreads();
        if (i != k) {
            Am[tid] = fmaf(-f, akj, Am[tid]);
            Iv[tid] = fmaf(-f, ikj, Iv[tid]);
        }
        __syncthreads();
    }

    float w = 0.f;
    #pragma unroll
    for (int k2 = 0; k2 < 12; ++k2) w = fmaf(Cm[i * 12 + k2], Iv[k2 * 12 + j], w);
    Wsh[tid] = w;
    __syncthreads();

    for (int item = tid; item < 180; item += 144) {
        const int cl  = item / 60;
        const int rem = item - cl * 60;
        const int ii  = rem / 5;
        const int s   = rem - ii * 5;
        const int rep = (cl == 0) ? 0 : ((cl == 1) ? 1 : 135);
        const int hb  = 3 * rep - 1;
        float acc = 0.f;
        #pragma unroll
        for (int jj = 0; jj < 12; ++jj) {
            float t = (float)(rep * 12 + jj);
            float p = (t - 1.5f) * 0.25f;
            p = fminf(fmaxf(p, 0.f), 407.f);
            int i0 = (int)p; if (i0 > 406) i0 = 406;
            float fr = p - (float)i0;
            int s0 = i0 - hb;
            float coef = (s == s0) ? (1.f - fr) : ((s == s0 + 1) ? fr : 0.f);
            acc = fmaf(Wsh[ii * 12 + jj], coef, acc);
        }
        g_Weff2[ub * 180 + item] = pk2(acc, acc);
    }
}

// ---------------- kernel B: phase + 4-avg + folded 5-tap stencil -------------
__global__ __launch_bounds__(256, 4) void kB(const float* __restrict__ lsr,
                                             const float* __restrict__ lsi,
                                             float2* __restrict__ out) {
    __shared__ float2 ph[LL];
    __shared__ ull    hv[RWS * RED];
    __shared__ ull    We2[180];

    const int tid  = threadIdx.x;
    const int row0 = blockIdx.x * RWS;
    const int ub   = row0 >> 6;

    if (tid < 180) We2[tid] = g_Weff2[ub * 180 + tid];
    const int m  = g_m[ub];
    const int mm = ((m % LL) + LL) % LL;

    {
        int q = (tid * mm) % LL;
        const int stp = (256 * mm) % LL;
        for (int n = tid; n < LL; n += 256) {
            ph[n] = g_phtab[q];
            q += stp; if (q >= LL) q -= LL;
        }
    }
    __syncthreads();

    // stage 1: phase-shifted 4-tap average, all 4 rows per iteration
    for (int rr = tid; rr < RED; rr += 256) {
        const int c0 = (row0) * LL + 4 * rr;
        const float4 xr0 = *(const float4*)(lsr + c0);
        const float4 xi0 = *(const float4*)(lsi + c0);
        const float4 xr1 = *(const float4*)(lsr + c0 + LL);
        const float4 xi1 = *(const float4*)(lsi + c0 + LL);
        const float4 xr2 = *(const float4*)(lsr + c0 + 2*LL);
        const float4 xi2 = *(const float4*)(lsi + c0 + 2*LL);
        const float4 xr3 = *(const float4*)(lsr + c0 + 3*LL);
        const float4 xi3 = *(const float4*)(lsi + c0 + 3*LL);
        const float2 p0 = ph[4*rr], p1 = ph[4*rr+1], p2 = ph[4*rr+2], p3 = ph[4*rr+3];

        #define AVG(xr, xi, dst) do { \
            float sr, si; \
            sr = (xr).x * p0.x;              si = (xr).x * p0.y; \
            sr = fmaf(-(xi).x, p0.y, sr);    si = fmaf( (xi).x, p0.x, si); \
            sr = fmaf( (xr).y, p1.x, sr);    si = fmaf( (xr).y, p1.y, si); \
            sr = fmaf(-(xi).y, p1.y, sr);    si = fmaf( (xi).y, p1.x, si); \
            sr = fmaf( (xr).z, p2.x, sr);    si = fmaf( (xr).z, p2.y, si); \
            sr = fmaf(-(xi).z, p2.y, sr);    si = fmaf( (xi).z, p2.x, si); \
            sr = fmaf( (xr).w, p3.x, sr);    si = fmaf( (xr).w, p3.y, si); \
            sr = fmaf(-(xi).w, p3.y, sr);    si = fmaf( (xi).w, p3.x, si); \
            hv[(dst) * RED + rr] = pk2(sr * 0.25f, si * 0.25f); } while (0)
        AVG(xr0, xi0, 0);
        AVG(xr1, xi1, 1);
        AVG(xr2, xi2, 2);
        AVG(xr3, xi3, 3);
        #undef AVG
    }
    __syncthreads();

    // stage 2: per (row, blk) -> 12 outputs, 2 at a time (low regs)
    for (int item = tid; item < RWS * 136; item += 256) {
        const int rl  = item / 136;
        const int blk = item - rl * 136;
        const int cl  = (blk == 0) ? 0 : ((blk == 135) ? 2 : 1);
        const ull* w  = &We2[cl * 60];
        const int hb  = 3 * blk - 1;
        const int hbase = rl * RED;

        ull h0, h1, h2, h3, h4;
        {
            int i0 = hb;     i0 = (i0 < 0) ? 0 : i0;
            int i4 = hb + 4; i4 = (i4 > RED-1) ? RED-1 : i4;
            h0 = hv[hbase + i0];
            h1 = hv[hbase + hb + 1];
            h2 = hv[hbase + hb + 2];
            h3 = hv[hbase + hb + 3];
            h4 = hv[hbase + i4];
        }

        float4* op = (float4*)(out + (row0 + rl) * LL + blk * 12);
        #pragma unroll
        for (int q = 0; q < 6; ++q) {
            const ull* wq = w + q * 10;
            ull a0 = mul2_(wq[0], h0);
            a0 = fma2_(wq[1], h1, a0);
            a0 = fma2_(wq[2], h2, a0);
            a0 = fma2_(wq[3], h3, a0);
            a0 = fma2_(wq[4], h4, a0);
            ull a1 = mul2_(wq[5], h0);
            a1 = fma2_(wq[6], h1, a1);
            a1 = fma2_(wq[7], h2, a1);
            a1 = fma2_(wq[8], h3, a1);
            a1 = fma2_(wq[9], h4, a1);
            float2 r0 = up2(a0), r1 = up2(a1);
            op[q] = make_float4(r0.x, r0.y, r1.x, r1.y);
        }
    }
}

// ---------------- launcher ----------------------------------------------------
extern "C" void kernel_launch(void* const* d_in, const int* in_sizes, int n_in,
                              void* d_out, int out_size) {
    const float* lsr = (const float*)d_in[0];
    const float* lsi = (const float*)d_in[1];
    const int*   cs  = (const int*)d_in[2];
    float2* out = (float2*)d_out;

    kP<<<9, 256>>>();
    kA<<<2048, 256>>>(lsr, lsi, cs);
    kS<<<NUP * NB, 144>>>(cs);
    kB<<<NUP * NB * NA / RWS, 256>>>(lsr, lsi, out);
    (void)in_sizes; (void)n_in; (void)out_size;
}

// round 16
// speedup vs baseline: 1.1739x; 1.1739x over previous
#include <cuda_runtime.h>
#include <math.h>

#define LL     1632
#define NUP    8
#define NB     32
#define NA     64
#define RED    408
#define RWS    4

typedef unsigned long long ull;

// ---------------- scratch (device globals) -----------------------------------
__device__ float2 g_phtab[LL];          // e^{2*pi*i*q/L}
__device__ float2 g_b12[12];            // e^{2*pi*i*r/12}
__device__ ull    g_wtc[5*416];         // odd bins o=1,3,5,7,9: packed {cos(n1),cos(n2)}
__device__ ull    g_wts[5*416];         // packed {sin(n1),sin(n2)}; n1=64j+lane, n2=n1+32
__device__ int    g_m[NUP*NB];
__device__ ull    g_Weff2[NUP*NB*180];  // per (u,b): 3 classes x 12 x 5, packed {w,w}
__device__ float  g_win[2048*21];
__device__ float  g_noise[2048];

// ---------------- f32x2 helpers ----------------------------------------------
__device__ __forceinline__ ull pk2(float a, float b) {
    ull r; asm("mov.b64 %0, {%1, %2};" : "=l"(r) : "f"(a), "f"(b)); return r;
}
__device__ __forceinline__ float2 up2(ull v) {
    float2 r; asm("mov.b64 {%0, %1}, %2;" : "=f"(r.x), "=f"(r.y) : "l"(v)); return r;
}
__device__ __forceinline__ ull fma2_(ull a, ull b, ull c) {
    ull d; asm("fma.rn.f32x2 %0, %1, %2, %3;" : "=l"(d) : "l"(a), "l"(b), "l"(c)); return d;
}
__device__ __forceinline__ ull mul2_(ull a, ull b) {
    ull d; asm("mul.rn.f32x2 %0, %1, %2;" : "=l"(d) : "l"(a), "l"(b)); return d;
}
__device__ __forceinline__ ull add2_(ull a, ull b) {
    ull d; asm("add.rn.f32x2 %0, %1, %2;" : "=l"(d) : "l"(a), "l"(b)); return d;
}
__device__ __forceinline__ ull sub2_(ull a, ull b) {
    ull d; asm("sub.rn.f32x2 %0, %1, %2;" : "=l"(d) : "l"(a), "l"(b)); return d;
}

// fp32 angle helper: ang = 2*pi * (q mod L) / L, exact integer mod first
__device__ __forceinline__ void sc_ang(int q, float* s, float* c) {
    const float TPF = 6.2831853071795864769f;
    int qm = q % LL; if (qm < 0) qm += LL;
    float ang = TPF * ((float)qm / (float)LL);
    sincosf(ang, s, c);
}

// ---------------- kernel P: tables (all fp32, no FP64) -----------------------
__global__ void kP() {
    int i = blockIdx.x * blockDim.x + threadIdx.x;
    if (i < LL) {
        float s, c; sc_ang(i, &s, &c);
        g_phtab[i] = make_float2(c, s);
    }
    if (i < 12) {
        const float TPF = 6.2831853071795864769f;
        float s, c; sincosf(TPF * (float)i / 12.0f, &s, &c);
        g_b12[i] = make_float2(c, s);
    }
    if (i < 5 * 416) {
        int o5 = i / 416, rem = i % 416;
        int j = rem / 32, lane = rem % 32;
        int o = 2 * o5 + 1;
        int n1 = 64 * j + lane, n2 = n1 + 32;
        float s1, c1, s2, c2;
        sc_ang(n1 * o, &s1, &c1);
        sc_ang(n2 * o, &s2, &c2);
        g_wtc[i] = pk2(c1, c2);
        g_wts[i] = pk2(s1, s2);
    }
}

// ---------------- kernel A (r14 exact) ----------------------------------------
__device__ __forceinline__ float wred(float v) {
    #pragma unroll
    for (int off = 16; off; off >>= 1) v += __shfl_xor_sync(0xffffffffu, v, off);
    return v;
}

__device__ __forceinline__ void scalar_step(
    const int k, const int lane, const int base, const int k12,
    const ull* wtc, const ull* wts, const float2* b12s,
    const float* __restrict__ lsr, const float* __restrict__ lsi,
    float* A, float* B, float* C, float* D,
    float& str, float& sti, float& nacc)
{
    const int n  = lane + (k << 5);
    const int nm = LL - n;
    const bool act = (n <= 816);
    const bool mir = (n >= 1 && n <= 815);
    const bool mnz = (n >= 2 && n <= 815);

    float2 b = b12s[(n * k12) % 12];

    float xr=0.f, xi=0.f, mr=0.f, mi=0.f;
    if (act) {
        xr = lsr[base+n]; xi = lsi[base+n];
        float yr = lsr[base+n+1], yi = lsi[base+n+1];
        float dr0 = yr-xr, di0 = yi-xi;
        nacc += dr0*dr0 + di0*di0;
    }
    if (mir) { mr = lsr[base+nm]; mi = lsi[base+nm]; }
    if (mnz) {
        float zr = lsr[base+nm+1], zi = lsi[base+nm+1];
        float er = zr-mr, ei = zi-mi;
        nacc += er*er + ei*ei;
    }
    if (!act) return;

    float gr = xr*b.x - xi*b.y,        gi = fmaf(xr, b.y, xi*b.x);
    float hr = fmaf(mi, b.y, mr*b.x),  hi = fmaf(mi, b.x, -(mr*b.y));
    float sr = gr+hr, dr = gr-hr, si = gi+hi, di = gi-hi;
    str += sr; sti += si;

    const int jj = k >> 1, half = k & 1;
    const int idx = jj * 32 + lane;
    float2 v;
    float c1,s1,c3,s3,c5,s5,c7,s7,c9,s9;
    v = up2(wtc[idx]);        c1 = half ? v.y : v.x;
    v = up2(wts[idx]);        s1 = half ? v.y : v.x;
    v = up2(wtc[416+idx]);    c3 = half ? v.y : v.x;
    v = up2(wts[416+idx]);    s3 = half ? v.y : v.x;
    v = up2(wtc[832+idx]);    c5 = half ? v.y : v.x;
    v = up2(wts[832+idx]);    s5 = half ? v.y : v.x;
    v = up2(wtc[1248+idx]);   c7 = half ? v.y : v.x;
    v = up2(wts[1248+idx]);   s7 = half ? v.y : v.x;
    v = up2(wtc[1664+idx]);   c9 = half ? v.y : v.x;
    v = up2(wts[1664+idx]);   s9 = half ? v.y : v.x;

    #define SACC(o, c, s) do { \
        A[o] = fmaf(sr, (c), A[o]); B[o] = fmaf(dr, (s), B[o]); \
        C[o] = fmaf(si, (c), C[o]); D[o] = fmaf(di, (s), D[o]); } while (0)
    SACC(0, c1, s1); SACC(2, c3, s3); SACC(4, c5, s5); SACC(6, c7, s7); SACC(8, c9, s9);
    float t1 = c1+c1;  float c2v = fmaf(t1, c1, -1.f),  s2v = t1*s1;   SACC(1, c2v, s2v);
    float t2 = c2v+c2v; float c4v = fmaf(t2, c2v, -1.f), s4v = t2*s2v;  SACC(3, c4v, s4v);
    float t3 = c3+c3;  float c6v = fmaf(t3, c3, -1.f),  s6v = t3*s3;   SACC(5, c6v, s6v);
    float t4 = c4v+c4v; float c8v = fmaf(t4, c4v, -1.f), s8v = t4*s4v;  SACC(7, c8v, s8v);
    float t5 = c5+c5;  float cav = fmaf(t5, c5, -1.f),  sav = t5*s5;   SACC(9, cav, sav);
    #undef SACC
}

__global__ __launch_bounds__(256, 2) void kA(const float* __restrict__ lsr,
                                             const float* __restrict__ lsi,
                                             const int*   __restrict__ cs) {
    __shared__ ull    wtc[5*416], wts[5*416];
    __shared__ ull    bpx[12], bpy[12], bpyn[12];
    __shared__ float2 b12s[12];
    __shared__ float  wpart[8][22];

    const int tid  = threadIdx.x;
    const int bid  = blockIdx.x;
    const int part = bid & 7;
    const int ub   = bid >> 3;
    const int u    = ub >> 5;

    int k12 = (12 - (cs[u] % 12)) % 12; if (k12 < 0) k12 += 12;
    const int st64 = (4 * k12) % 12;

    for (int i = tid; i < 5*416; i += 256) { wtc[i] = g_wtc[i]; wts[i] = g_wts[i]; }
    if (tid < 12) {
        float2 b0 = g_b12[tid];
        float2 b1 = g_b12[(tid + (8 * k12) % 12) % 12];
        b12s[tid] = b0;
        bpx[tid]  = pk2(b0.x, b1.x);
        bpy[tid]  = pk2(b0.y, b1.y);
        bpyn[tid] = pk2(-b0.y, -b1.y);
    }
    __syncthreads();

    const int lane = tid & 31;
    const int warp = tid >> 5;
    const int a    = part * 8 + warp;
    const int base = (ub * 64 + a) * LL;

    ull A[10], B[10], C[10], D[10];
    #pragma unroll
    for (int o = 0; o < 10; ++o) { A[o]=0ull; B[o]=0ull; C[o]=0ull; D[o]=0ull; }
    ull strp = 0ull, stip = 0ull, naccp = 0ull;
    const ull NEG1 = pk2(-1.f, -1.f);

    int r = ((lane + 64) * k12) % 12;

    int n1  = lane + 64;
    int nm1 = LL - n1;
    ull xr = pk2(lsr[base+n1],     lsr[base+n1+32]);
    ull xi = pk2(lsi[base+n1],     lsi[base+n1+32]);
    ull yr = pk2(lsr[base+n1+1],   lsr[base+n1+33]);
    ull yi = pk2(lsi[base+n1+1],   lsi[base+n1+33]);
    ull mr = pk2(lsr[base+nm1],    lsr[base+nm1-32]);
    ull mi = pk2(lsi[base+nm1],    lsi[base+nm1-32]);
    ull zr = pk2(lsr[base+nm1+1],  lsr[base+nm1-31]);
    ull zi = pk2(lsi[base+nm1+1],  lsi[base+nm1-31]);

    for (int j = 1; j <= 11; ++j) {
        const ull cxr=xr, cxi=xi, cyr=yr, cyi=yi, cmr=mr, cmi=mi, czr=zr, czi=zi;
        {
            const int n2  = n1 + 64;
            const int nm2 = LL - n2;
            xr = pk2(lsr[base+n2],     lsr[base+n2+32]);
            xi = pk2(lsi[base+n2],     lsi[base+n2+32]);
            yr = pk2(lsr[base+n2+1],   lsr[base+n2+33]);
            yi = pk2(lsi[base+n2+1],   lsi[base+n2+33]);
            mr = pk2(lsr[base+nm2],    lsr[base+nm2-32]);
            mi = pk2(lsi[base+nm2],    lsi[base+nm2-32]);
            zr = pk2(lsr[base+nm2+1],  lsr[base+nm2-31]);
            zi = pk2(lsi[base+nm2+1],  lsi[base+nm2-31]);
            n1 = n2;
        }
        ull dd;
        dd = sub2_(cyr, cxr); naccp = fma2_(dd, dd, naccp);
        dd = sub2_(cyi, cxi); naccp = fma2_(dd, dd, naccp);
        dd = sub2_(czr, cmr); naccp = fma2_(dd, dd, naccp);
        dd = sub2_(czi, cmi); naccp = fma2_(dd, dd, naccp);
        ull bx = bpx[r], by = bpy[r], byn = bpyn[r];
        r += st64; if (r >= 12) r -= 12;
        ull gr = fma2_(cxi, byn, mul2_(cxr, bx));
        ull gi = fma2_(cxi, bx,  mul2_(cxr, by));
        ull hr = fma2_(cmi, by,  mul2_(cmr, bx));
        ull hi = fma2_(cmi, bx,  mul2_(cmr, byn));
        ull sr = add2_(gr, hr), dr = sub2_(gr, hr);
        ull si = add2_(gi, hi), di = sub2_(gi, hi);
        strp = add2_(strp, sr); stip = add2_(stip, si);
        const int idx = (j << 5) + lane;
        ull w1c = wtc[idx],       w1s = wts[idx];
        ull w3c = wtc[416+idx],   w3s = wts[416+idx];
        ull w5c = wtc[832+idx],   w5s = wts[832+idx];
        ull w7c = wtc[1248+idx],  w7s = wts[1248+idx];
        ull w9c = wtc[1664+idx],  w9s = wts[1664+idx];

        #define PACC(o, c, s) do { \
            A[o] = fma2_(sr, (c), A[o]); B[o] = fma2_(dr, (s), B[o]); \
            C[o] = fma2_(si, (c), C[o]); D[o] = fma2_(di, (s), D[o]); } while (0)
        PACC(0, w1c, w1s); PACC(2, w3c, w3s); PACC(4, w5c, w5s);
        PACC(6, w7c, w7s); PACC(8, w9c, w9s);
        ull t, c2v, s2v, c4v, s4v;
        t = add2_(w1c, w1c); c2v = fma2_(t, w1c, NEG1); s2v = mul2_(t, w1s); PACC(1, c2v, s2v);
        t = add2_(c2v, c2v); c4v = fma2_(t, c2v, NEG1); s4v = mul2_(t, s2v); PACC(3, c4v, s4v);
        t = add2_(w3c, w3c); ull c6v = fma2_(t, w3c, NEG1), s6v = mul2_(t, w3s); PACC(5, c6v, s6v);
        t = add2_(c4v, c4v); ull c8v = fma2_(t, c4v, NEG1), s8v = mul2_(t, s4v); PACC(7, c8v, s8v);
        t = add2_(w5c, w5c); ull cav = fma2_(t, w5c, NEG1), sav = mul2_(t, w5s); PACC(9, cav, sav);
        #undef PACC
    }

    float Af[10], Bf[10], Cf[10], Df[10];
    #pragma unroll
    for (int o = 0; o < 10; ++o) {
        float2 v;
        v = up2(A[o]); Af[o] = v.x + v.y;
        v = up2(B[o]); Bf[o] = v.x + v.y;
        v = up2(C[o]); Cf[o] = v.x + v.y;
        v = up2(D[o]); Df[o] = v.x + v.y;
    }
    float2 vv;
    vv = up2(strp);  float str = vv.x + vv.y;
    vv = up2(stip);  float sti = vv.x + vv.y;
    vv = up2(naccp); float nacc = vv.x + vv.y;

    scalar_step(0,  lane, base, k12, wtc, wts, b12s, lsr, lsi, Af, Bf, Cf, Df, str, sti, nacc);
    scalar_step(1,  lane, base, k12, wtc, wts, b12s, lsr, lsi, Af, Bf, Cf, Df, str, sti, nacc);
    scalar_step(24, lane, base, k12, wtc, wts, b12s, lsr, lsi, Af, Bf, Cf, Df, str, sti, nacc);
    scalar_step(25, lane, base, k12, wtc, wts, b12s, lsr, lsi, Af, Bf, Cf, Df, str, sti, nacc);

    #pragma unroll
    for (int o = 0; o < 10; ++o) {
        Af[o]=wred(Af[o]); Bf[o]=wred(Bf[o]); Cf[o]=wred(Cf[o]); Df[o]=wred(Df[o]);
    }
    str=wred(str); sti=wred(sti); nacc=wred(nacc);

    if (lane == 0) {
        wpart[warp][10] = str*str + sti*sti;
        #pragma unroll
        for (int o = 0; o < 10; ++o) {
            float rp = Af[o]-Df[o], ip = Bf[o]+Cf[o];
            wpart[warp][11+o] = rp*rp + ip*ip;
            float rm = Af[o]+Df[o], im = Cf[o]-Bf[o];
            wpart[warp][9-o]  = rm*rm + im*im;
        }
        wpart[warp][21] = nacc;
    }
    __syncthreads();
    if (tid < 22) {
        float s = 0.f;
        #pragma unroll
        for (int w = 0; w < 8; ++w) s += wpart[w][tid];
        if (tid < 21) g_win[bid * 21 + tid] = s;
        else          g_noise[bid] = s;
    }
}

// ---------------- kernel S: argmax + Wiener solve + packed Weff (fp32 only) --
__global__ void kS(const int* __restrict__ cs) {
    __shared__ float win[21];
    __shared__ float Cm[144], Am[144], Iv[144], Wsh[144];
    __shared__ float s_sh;

    const int ub = blockIdx.x;
    const int tid = threadIdx.x;           // 144 threads
    const int u = ub >> 5;
    const int i = tid / 12, j = tid % 12;

    if (tid < 21) {
        float s = 0.f;
        #pragma unroll
        for (int p = 0; p < 8; ++p) s += g_win[(ub * 8 + p) * 21 + tid];
        win[tid] = s;
    }
    if (tid == 21) {
        float s = 0.f;
        #pragma unroll
        for (int p = 0; p < 8; ++p) s += g_noise[ub * 8 + p];
        s_sh = s / (64.0f * 1631.0f * 2.0f);
    }
    __syncthreads();

    if (tid == 0) {
        int bi = 0; float bv = win[0];
        for (int q = 1; q < 21; ++q) if (win[q] > bv) { bv = win[q]; bi = q; }
        int k12 = (12 - (cs[u] % 12)) % 12; if (k12 < 0) k12 += 12;
        g_m[ub] = k12 * 136 + (bi - 10);
    }

    int d = i - j; if (d < 0) d = -d;
    // fp32 0.9^d (no FP64 pow)
    float c = 1.0f;
    for (int q = 0; q < d; ++q) c *= 0.9f;
    Cm[tid] = c;
    Am[tid] = c + ((i == j) ? s_sh : 0.f);
    Iv[tid] = (i == j) ? 1.f : 0.f;
    __syncthreads();

    for (int k = 0; k < 12; ++k) {
        float piv = Am[k * 12 + k];
        __syncthreads();
        if (i == k) {
            float ip = 1.0f / piv;
            Am[tid] *= ip; Iv[tid] *= ip;
        }
        __syncthreads();
        float f   = Am[i * 12 + k];
        float akj = Am[k * 12 + j];
        float ikj = Iv[k * 12 + j];
        __syncthreads();
        if (i != k) {
            Am[tid] = fmaf(-f, akj, Am[tid]);
            Iv[tid] = fmaf(-f, ikj, Iv[tid]);
        }
        __syncthreads();
    }

    float w = 0.f;
    #pragma unroll
    for (int k2 = 0; k2 < 12; ++k2) w = fmaf(Cm[i * 12 + k2], Iv[k2 * 12 + j], w);
    Wsh[tid] = w;
    __syncthreads();

    for (int item = tid; item < 180; item += 144) {
        const int cl  = item / 60;
        const int rem = item - cl * 60;
        const int ii  = rem / 5;
        const int s   = rem - ii * 5;
        const int rep = (cl == 0) ? 0 : ((cl == 1) ? 1 : 135);
        const int hb  = 3 * rep - 1;
        float acc = 0.f;
        #pragma unroll
        for (int jj = 0; jj < 12; ++jj) {
            float t = (float)(rep * 12 + jj);
            float p = (t - 1.5f) * 0.25f;
            p = fminf(fmaxf(p, 0.f), 407.f);
            int i0 = (int)p; if (i0 > 406) i0 = 406;
            float fr = p - (float)i0;
            int s0 = i0 - hb;
            float coef = (s == s0) ? (1.f - fr) : ((s == s0 + 1) ? fr : 0.f);
            acc = fmaf(Wsh[ii * 12 + jj], coef, acc);
        }
        g_Weff2[ub * 180 + item] = pk2(acc, acc);
    }
}

// ---------------- kernel B (r14 exact) ----------------------------------------
__global__ __launch_bounds__(256, 4) void kB(const float* __restrict__ lsr,
                                             const float* __restrict__ lsi,
                                             float2* __restrict__ out) {
    __shared__ float2 ph[LL];
    __shared__ ull    hv[RWS * RED];
    __shared__ ull    We2[180];

    const int tid  = threadIdx.x;
    const int row0 = blockIdx.x * RWS;
    const int ub   = row0 >> 6;

    if (tid < 180) We2[tid] = g_Weff2[ub * 180 + tid];
    const int m  = g_m[ub];
    const int mm = ((m % LL) + LL) % LL;

    {
        int q = (tid * mm) % LL;
        const int stp = (256 * mm) % LL;
        for (int n = tid; n < LL; n += 256) {
            ph[n] = g_phtab[q];
            q += stp; if (q >= LL) q -= LL;
        }
    }
    __syncthreads();

    for (int rr = tid; rr < RED; rr += 256) {
        const int c0 = (row0) * LL + 4 * rr;
        const float4 xr0 = *(const float4*)(lsr + c0);
        const float4 xi0 = *(const float4*)(lsi + c0);
        const float4 xr1 = *(const float4*)(lsr + c0 + LL);
        const float4 xi1 = *(const float4*)(lsi + c0 + LL);
        const float4 xr2 = *(const float4*)(lsr + c0 + 2*LL);
        const float4 xi2 = *(const float4*)(lsi + c0 + 2*LL);
        const float4 xr3 = *(const float4*)(lsr + c0 + 3*LL);
        const float4 xi3 = *(const float4*)(lsi + c0 + 3*LL);
        const float2 p0 = ph[4*rr], p1 = ph[4*rr+1], p2 = ph[4*rr+2], p3 = ph[4*rr+3];

        #define AVG(xr, xi, dst) do { \
            float sr, si; \
            sr = (xr).x * p0.x;              si = (xr).x * p0.y; \
            sr = fmaf(-(xi).x, p0.y, sr);    si = fmaf( (xi).x, p0.x, si); \
            sr = fmaf( (xr).y, p1.x, sr);    si = fmaf( (xr).y, p1.y, si); \
            sr = fmaf(-(xi).y, p1.y, sr);    si = fmaf( (xi).y, p1.x, si); \
            sr = fmaf( (xr).z, p2.x, sr);    si = fmaf( (xr).z, p2.y, si); \
            sr = fmaf(-(xi).z, p2.y, sr);    si = fmaf( (xi).z, p2.x, si); \
            sr = fmaf( (xr).w, p3.x, sr);    si = fmaf( (xr).w, p3.y, si); \
            sr = fmaf(-(xi).w, p3.y, sr);    si = fmaf( (xi).w, p3.x, si); \
            hv[(dst) * RED + rr] = pk2(sr * 0.25f, si * 0.25f); } while (0)
        AVG(xr0, xi0, 0);
        AVG(xr1, xi1, 1);
        AVG(xr2, xi2, 2);
        AVG(xr3, xi3, 3);
        #undef AVG
    }
    __syncthreads();

    for (int item = tid; item < RWS * 136; item += 256) {
        const int rl  = item / 136;
        const int blk = item - rl * 136;
        const int cl  = (blk == 0) ? 0 : ((blk == 135) ? 2 : 1);
        const ull* w  = &We2[cl * 60];
        const int hb  = 3 * blk - 1;
        const int hbase = rl * RED;

        ull h0, h1, h2, h3, h4;
        {
            int i0 = hb;     i0 = (i0 < 0) ? 0 : i0;
            int i4 = hb + 4; i4 = (i4 > RED-1) ? RED-1 : i4;
            h0 = hv[hbase + i0];
            h1 = hv[hbase + hb + 1];
            h2 = hv[hbase + hb + 2];
            h3 = hv[hbase + hb + 3];
            h4 = hv[hbase + i4];
        }

        float4* op = (float4*)(out + (row0 + rl) * LL + blk * 12);
        #pragma unroll
        for (int q = 0; q < 6; ++q) {
            const ull* wq = w + q * 10;
            ull a0 = mul2_(wq[0], h0);
            a0 = fma2_(wq[1], h1, a0);
            a0 = fma2_(wq[2], h2, a0);
            a0 = fma2_(wq[3], h3, a0);
            a0 = fma2_(wq[4], h4, a0);
            ull a1 = mul2_(wq[5], h0);
            a1 = fma2_(wq[6], h1, a1);
            a1 = fma2_(wq[7], h2, a1);
            a1 = fma2_(wq[8], h3, a1);
            a1 = fma2_(wq[9], h4, a1);
            float2 r0 = up2(a0), r1 = up2(a1);
            op[q] = make_float4(r0.x, r0.y, r1.x, r1.y);
        }
    }
}

// ---------------- launcher ----------------------------------------------------
extern "C" void kernel_launch(void* const* d_in, const int* in_sizes, int n_in,
                              void* d_out, int out_size) {
    const float* lsr = (const float*)d_in[0];
    const float* lsi = (const float*)d_in[1];
    const int*   cs  = (const int*)d_in[2];
    float2* out = (float2*)d_out;

    kP<<<9, 256>>>();
    kA<<<2048, 256>>>(lsr, lsi, cs);
    kS<<<NUP * NB, 144>>>(cs);
    kB<<<NUP * NB * NA / RWS, 256>>>(lsr, lsi, out);
    (void)in_sizes; (void)n_in; (void)out_size;
}